// round 1
// baseline (speedup 1.0000x reference)
#include <cuda_runtime.h>
#include <math.h>

#define NSENT 8192
#define C     1024
#define NCTA  64                 // CTAs per direction
#define COLS  16                 // columns owned per CTA (one per warp)
#define NTHREADS 512             // 16 warps
#define NCTA_TOTAL (2*NCTA)
#define DRIFT 8.0f

// -------- device scratch (no allocations allowed) --------
__device__ float    g_E [C*C];          // exp(T), row-major [k][j]  (beta uses rows)
__device__ float    g_ET[C*C];          // transpose [j][k]          (alpha uses rows)
__device__ float    g_beta[(size_t)NSENT*C];
__device__ float    g_pA[2*C];          // double-buffered scaled alpha probs
__device__ float    g_pB[2*C];
__device__ unsigned g_MA[NSENT];        // per-step max(alpha[t]) (order-encoded)
__device__ unsigned g_MB[NSENT];
__device__ unsigned g_cnt[3*32];        // barrier counters (padded)
__device__ unsigned g_gen[3*32];        // barrier generations (padded)

// order-preserving float<->uint encoding for atomicMax
__device__ __forceinline__ unsigned encf(float f) {
    unsigned u = __float_as_uint(f);
    return (u & 0x80000000u) ? ~u : (u | 0x80000000u);
}
__device__ __forceinline__ float decf(unsigned u) {
    return __uint_as_float((u & 0x80000000u) ? (u ^ 0x80000000u) : ~u);
}

// generation-counter grid barrier (subset of CTAs identified by id)
__device__ __forceinline__ void gbar(int id, unsigned target, unsigned count) {
    __syncthreads();
    if (threadIdx.x == 0) {
        volatile unsigned* cnt = &g_cnt[id*32];
        volatile unsigned* gen = &g_gen[id*32];
        __threadfence();
        unsigned arrived = atomicAdd((unsigned*)&g_cnt[id*32], 1u);
        if (arrived == count - 1u) {
            *cnt = 0u;
            __threadfence();
            *gen = target;
        } else {
            while (*gen < target) { }
            __threadfence();
        }
    }
    __syncthreads();
}

// -------- init kernel: E = exp(T), E^T, reset barriers / max arrays --------
__global__ void crf_init(const float* __restrict__ T) {
    int idx = blockIdx.x * blockDim.x + threadIdx.x;
    if (idx < C*C) {
        float e = expf(T[idx]);
        g_E[idx] = e;
        int k = idx / C, j = idx % C;
        g_ET[j*C + k] = e;
    }
    if (idx < NSENT) { g_MA[idx] = 0u; g_MB[idx] = 0u; }
    if (idx < 3*32)  { g_cnt[idx] = 0u; g_gen[idx] = 0u; }
}

// -------- persistent forward+backward kernel --------
__global__ void __launch_bounds__(NTHREADS) crf_main(const float* __restrict__ scores,
                                                     float* __restrict__ out) {
    const int  cta    = blockIdx.x;
    const bool isBeta = (cta >= NCTA);
    const int  grp    = isBeta ? (cta - NCTA) : cta;
    const int  warp   = threadIdx.x >> 5;
    const int  lane   = threadIdx.x & 31;
    const int  j      = grp * COLS + warp;    // column (alpha) / row (beta) owned

    __shared__ float p_sm[C];
    __shared__ float warpmax[COLS];
    __shared__ float redsum[COLS];

    // E coefficients for this warp's column, 32 regs/thread, loaded once.
    // mapping: element k = 128*u + 4*lane + v  ->  Ereg[u].{x,y,z,w}
    float4 Ereg[8];
    {
        const float* Emat = isBeta ? g_E : g_ET;
        const float4* Erow = (const float4*)(Emat + (size_t)j * C);
        #pragma unroll
        for (int u = 0; u < 8; u++) Ereg[u] = Erow[u*32 + lane];
    }

    float*    pbuf    = isBeta ? g_pB : g_pA;
    unsigned* MArr    = isBeta ? g_MB : g_MA;
    float*    rowsOut = isBeta ? g_beta : out;   // alpha goes straight into d_out
    const int barid   = isBeta ? 1 : 0;

    // ---- step 0: alpha[0]=scores[0], beta[N-1]=scores[N-1], scale c0 = 0
    {
        const int row0 = isBeta ? (NSENT - 1) : 0;
        if (lane == 0) {
            float a0 = __ldg(&scores[(size_t)row0 * C + j]);
            rowsOut[(size_t)row0 * C + j] = a0;
            pbuf[j] = expf(a0);
            warpmax[warp] = a0;
            __threadfence();
        }
        __syncthreads();
        if (threadIdx.x == 0) {
            float m = warpmax[0];
            #pragma unroll
            for (int w = 1; w < COLS; w++) m = fmaxf(m, warpmax[w]);
            atomicMax(&MArr[0], encf(m));
        }
    }
    gbar(barid, 1u, NCTA);

    // ---- main recurrence: 8191 dependent rounds
    float c_prev = 0.0f;   // scale under which p of previous step was stored
    for (int t = 1; t < NSENT; t++) {
        const int    row  = isBeta ? (NSENT - 1 - t) : t;
        const float* pin  = pbuf + ((t - 1) & 1) * C;
        float*       pout = pbuf + (t & 1) * C;

        // exact (lagged) max of previous step -> scale for this step's p
        float c_t = decf(__ldcg(&MArr[t - 1])) + DRIFT;

        // stage p (4KB) through smem, L2-coherent load
        {
            const float2* pin2 = (const float2*)pin;
            float2 pv = __ldcg(&pin2[threadIdx.x]);
            ((float2*)p_sm)[threadIdx.x] = pv;
        }
        __syncthreads();

        // matvec for this warp's column: 4 independent FMA chains
        float ax = 0.f, ay = 0.f, az = 0.f, aw = 0.f;
        const float4* p4 = (const float4*)p_sm;
        #pragma unroll
        for (int u = 0; u < 8; u++) {
            float4 p = p4[u*32 + lane];
            ax = fmaf(p.x, Ereg[u].x, ax);
            ay = fmaf(p.y, Ereg[u].y, ay);
            az = fmaf(p.z, Ereg[u].z, az);
            aw = fmaf(p.w, Ereg[u].w, aw);
        }
        float acc = (ax + ay) + (az + aw);
        #pragma unroll
        for (int s = 16; s > 0; s >>= 1)
            acc += __shfl_xor_sync(0xFFFFFFFFu, acc, s);

        if (lane == 0) {
            float a = __ldg(&scores[(size_t)row * C + j]) + c_prev + logf(acc);
            rowsOut[(size_t)row * C + j] = a;
            pout[j] = expf(a - c_t);
            warpmax[warp] = a;
            __threadfence();   // make this lane's global stores gpu-visible
        }
        __syncthreads();
        if (threadIdx.x == 0) {
            float m = warpmax[0];
            #pragma unroll
            for (int w = 1; w < COLS; w++) m = fmaxf(m, warpmax[w]);
            atomicMax(&MArr[t], encf(m));
        }
        c_prev = c_t;
        gbar(barid, (unsigned)(t + 1), NCTA);
    }

    // ---- join both directions
    gbar(2, 1u, NCTA_TOTAL);

    // ---- Z = LSE(alpha[N-1]) = c_last + log(sum p_final), computed by every CTA
    float Z;
    {
        const float2* pz = (const float2*)(g_pA + ((NSENT - 1) & 1) * C);
        float2 v = __ldcg(&pz[threadIdx.x]);
        float zs = v.x + v.y;
        #pragma unroll
        for (int s = 16; s > 0; s >>= 1)
            zs += __shfl_xor_sync(0xFFFFFFFFu, zs, s);
        if (lane == 0) redsum[warp] = zs;
        __syncthreads();
        if (warp == 0) {
            float s = (lane < COLS) ? redsum[lane] : 0.0f;
            #pragma unroll
            for (int sh = 8; sh > 0; sh >>= 1)
                s += __shfl_xor_sync(0xFFFFFFFFu, s, sh);
            if (lane == 0) redsum[0] = s;
        }
        __syncthreads();
        float c_last = decf(__ldcg(&g_MA[NSENT - 2])) + DRIFT;
        Z = c_last + logf(redsum[0]);
    }

    // ---- marginals: out = alpha(out) + beta - scores - Z  (streaming, float4)
    {
        const size_t total4 = (size_t)NSENT * C / 4;
        const size_t tid    = (size_t)cta * NTHREADS + threadIdx.x;
        const size_t nthr   = (size_t)NCTA_TOTAL * NTHREADS;
        const float4* b4 = (const float4*)g_beta;
        const float4* s4 = (const float4*)scores;
        float4* o4 = (float4*)out;
        for (size_t i = tid; i < total4; i += nthr) {
            float4 a = __ldcg(&o4[i]);
            float4 b = __ldcg(&b4[i]);
            float4 s = __ldg(&s4[i]);
            float4 r;
            r.x = a.x + b.x - s.x - Z;
            r.y = a.y + b.y - s.y - Z;
            r.z = a.z + b.z - s.z - Z;
            r.w = a.w + b.w - s.w - Z;
            o4[i] = r;
        }
    }
}

extern "C" void kernel_launch(void* const* d_in, const int* in_sizes, int n_in,
                              void* d_out, int out_size) {
    const float* scores = (const float*)d_in[0];   // [8192*1024] f32
    const float* T      = (const float*)d_in[1];   // [1024*1024] f32
    float* out = (float*)d_out;                    // [8192*1024] f32

    crf_init<<<(C*C + 255) / 256, 256>>>(T);
    crf_main<<<NCTA_TOTAL, NTHREADS>>>(scores, out);
}

// round 5
// speedup vs baseline: 1.0481x; 1.0481x over previous
#include <cuda_runtime.h>
#include <math.h>

#define NSENT 8192
#define C     1024
#define NCTA  64                 // CTAs per direction
#define COLS  16                 // columns owned per CTA (one per warp)
#define NTHREADS 512             // 16 warps
#define NCTA_TOTAL (2*NCTA)
#define DRIFT 8.0f
#define FSTRIDE 8                // 32B between flag words
#define ROWS_PER_CTA (NSENT / NCTA_TOTAL)   // 64 rows per CTA in epilogue

// -------- device scratch (no allocations allowed) --------
__device__ float    g_E [C*C];          // exp(T) row-major [k][j]   (beta)
__device__ float    g_ET[C*C];          // transpose [j][k]          (alpha)
__device__ float    g_beta[(size_t)NSENT*C];     // centered beta
__device__ float    g_pA[2*C];          // double-buffered scaled alpha probs
__device__ float    g_pB[2*C];
__device__ double   g_offA[NSENT];      // alpha row offsets C_{t-1} (double!)
__device__ double   g_offB[NSENT];      // beta row offsets
__device__ double   g_Zbase;            // C_{N-1} for alpha (Z = Zbase + log sum p)
__device__ unsigned g_flags[2*NCTA*FSTRIDE];     // per-direction producer flags
__device__ unsigned g_jflags[NCTA_TOTAL*FSTRIDE];// join barrier flags

__device__ __forceinline__ unsigned ld_acq(const unsigned* p) {
    unsigned v;
    asm volatile("ld.acquire.gpu.global.u32 %0, [%1];" : "=r"(v) : "l"(p) : "memory");
    return v;
}
__device__ __forceinline__ void st_rel(unsigned* p, unsigned v) {
    asm volatile("st.release.gpu.global.u32 [%0], %1;" :: "l"(p), "r"(v) : "memory");
}

// -------- init kernel: E = exp(T), E^T, reset flags --------
__global__ void crf_init(const float* __restrict__ T) {
    int idx = blockIdx.x * blockDim.x + threadIdx.x;
    if (idx < C*C) {
        float e = expf(T[idx]);
        g_E[idx] = e;
        int k = idx / C, j = idx % C;
        g_ET[j*C + k] = e;
    }
    if (idx < 2*NCTA*FSTRIDE)      g_flags[idx]  = 0u;
    if (idx < NCTA_TOTAL*FSTRIDE)  g_jflags[idx] = 0u;
}

// -------- persistent forward+backward kernel --------
__global__ void __launch_bounds__(NTHREADS) crf_main(const float* __restrict__ scores,
                                                     float* __restrict__ out) {
    const int  cta    = blockIdx.x;
    const bool isBeta = (cta >= NCTA);
    const int  grp    = isBeta ? (cta - NCTA) : cta;
    const int  warp   = threadIdx.x >> 5;
    const int  lane   = threadIdx.x & 31;
    const int  j      = grp * COLS + warp;    // column (alpha) / row (beta) owned

    __shared__ float p_sm[C];
    __shared__ float redsum[COLS];
    __shared__ float k_sm[ROWS_PER_CTA];

    // E coefficients for this warp's column, 32 regs/thread, loaded once.
    float4 Ereg[8];
    {
        const float* Emat = isBeta ? g_E : g_ET;
        const float4* Erow = (const float4*)(Emat + (size_t)j * C);
        #pragma unroll
        for (int u = 0; u < 8; u++) Ereg[u] = Erow[u*32 + lane];
    }

    float*    pbuf    = isBeta ? g_pB : g_pA;
    float*    rowsOut = isBeta ? g_beta : out;      // centered alpha -> d_out
    double*   offArr  = isBeta ? g_offB : g_offA;
    unsigned* flags   = g_flags + (isBeta ? NCTA*FSTRIDE : 0);

    // scale-offset bookkeeping: thread 0 of grp-0 CTAs only, in double, OFF the
    // critical path (the p-chain never consumes Cd).
    double Cd = 0.0;
    const bool keeper = (grp == 0) && (threadIdx.x == 0);

    // ---- step 0: a_hat[row0] = scores[row0], scale C_0 = 0
    float s_pref = 0.0f;
    {
        const int row0 = isBeta ? (NSENT - 1) : 0;
        if (lane == 0) {
            float a0 = __ldg(&scores[(size_t)row0 * C + j]);
            rowsOut[(size_t)row0 * C + j] = a0;      // centered (offset 0)
            pbuf[j] = expf(a0);                      // buffer 0, scale 0
            const int row1 = isBeta ? (NSENT - 2) : 1;
            s_pref = __ldg(&scores[(size_t)row1 * C + j]);
        }
        if (keeper) offArr[row0] = 0.0;
        __syncthreads();
        if (threadIdx.x == 0) st_rel(&flags[grp*FSTRIDE], 1u);
    }

    // ---- main recurrence: 8191 dependent rounds
    for (int t = 1; t < NSENT; t++) {
        const int row = isBeta ? (NSENT - 1 - t) : t;

        // rotate score prefetch (lane0 only); issue next load before the wait
        float s_val = s_pref;
        if (lane == 0) {
            int tn = (t + 1 < NSENT) ? (t + 1) : t;
            int rown = isBeta ? (NSENT - 1 - tn) : tn;
            s_pref = __ldg(&scores[(size_t)rown * C + j]);
        }

        // flag-array barrier fused with chunk staging: thread i waits on
        // producer i then immediately fetches producer i's 64B chunk.
        {
            const float4* pin4 = (const float4*)(pbuf + ((t - 1) & 1) * C);
            if (threadIdx.x < NCTA) {
                const unsigned* fp = &flags[threadIdx.x * FSTRIDE];
                while (ld_acq(fp) < (unsigned)t) { }
                const float4* src = pin4 + threadIdx.x * 4;
                float4 v0 = __ldcg(&src[0]);
                float4 v1 = __ldcg(&src[1]);
                float4 v2 = __ldcg(&src[2]);
                float4 v3 = __ldcg(&src[3]);
                float4* dst = ((float4*)p_sm) + threadIdx.x * 4;
                dst[0] = v0; dst[1] = v1; dst[2] = v2; dst[3] = v3;
            }
            __syncthreads();
        }

        // matvec for this warp's column + running max of p (ALU pipe, dual-issue)
        float ax = 0.f, ay = 0.f, az = 0.f, aw = 0.f;
        float mx = 0.f, my = 0.f, mz = 0.f, mw = 0.f;
        const float4* p4 = (const float4*)p_sm;
        #pragma unroll
        for (int u = 0; u < 8; u++) {
            float4 p = p4[u*32 + lane];
            ax = fmaf(p.x, Ereg[u].x, ax);  mx = fmaxf(mx, p.x);
            ay = fmaf(p.y, Ereg[u].y, ay);  my = fmaxf(my, p.y);
            az = fmaf(p.z, Ereg[u].z, az);  mz = fmaxf(mz, p.z);
            aw = fmaf(p.w, Ereg[u].w, aw);  mw = fmaxf(mw, p.w);
        }
        float acc = (ax + ay) + (az + aw);
        float mxp = fmaxf(fmaxf(mx, my), fmaxf(mz, mw));
        #pragma unroll
        for (int s = 16; s > 0; s >>= 1) {
            acc += __shfl_xor_sync(0xFFFFFFFFu, acc, s);
            mxp  = fmaxf(mxp, __shfl_xor_sync(0xFFFFFFFFu, mxp, s));
        }

        float ahat = 0.0f;
        float lm;
        if (lane == 0) {
            // lm shifts the scale only; it cancels analytically next step.
            lm = __logf(mxp);                 // bit-identical in every CTA
            float la = logf(acc);             // chain path: accurate
            ahat = s_val + la;                // CENTERED alpha/beta (small!)
            float* pout = pbuf + (t & 1) * C;
            pout[j] = expf(ahat - lm - DRIFT);   // scale C_t = C_{t-1}+lm+DRIFT
        }
        __syncthreads();                      // all pout chunks of this CTA done
        if (threadIdx.x == 0) st_rel(&flags[grp*FSTRIDE], (unsigned)(t + 1));
        // off the release path:
        if (keeper) {
            offArr[row] = Cd;                 // offset of row t is C_{t-1}
            Cd += (double)(lm + DRIFT);       // exact bookkeeping in double
        }
        if (lane == 0) rowsOut[(size_t)row * C + j] = ahat;
    }

    // final rowsOut stores must happen-before the join release
    if (keeper && !isBeta) g_Zbase = Cd;      // C_{N-1} for alpha
    __syncthreads();

    // ---- join both directions (release/acquire flag barrier)
    if (threadIdx.x == 0) st_rel(&g_jflags[cta*FSTRIDE], 1u);
    if (threadIdx.x < NCTA_TOTAL) {
        const unsigned* fp = &g_jflags[threadIdx.x * FSTRIDE];
        while (ld_acq(fp) < 1u) { }
    }
    __syncthreads();

    // ---- Z = Zbase + log(sum p_final), computed redundantly by every CTA
    double Zd;
    {
        const float2* pz = (const float2*)(g_pA + ((NSENT - 1) & 1) * C);
        float2 v = __ldcg(&pz[threadIdx.x]);
        float zs = v.x + v.y;
        #pragma unroll
        for (int s = 16; s > 0; s >>= 1)
            zs += __shfl_xor_sync(0xFFFFFFFFu, zs, s);
        if (lane == 0) redsum[warp] = zs;
        __syncthreads();
        if (warp == 0) {
            float s = (lane < COLS) ? redsum[lane] : 0.0f;
            #pragma unroll
            for (int sh = 8; sh > 0; sh >>= 1)
                s += __shfl_xor_sync(0xFFFFFFFFu, s, sh);
            if (lane == 0) redsum[0] = s;
        }
        __syncthreads();
        Zd = g_Zbase + (double)logf(redsum[0]);
    }

    // ---- per-row combine constants K[i] = offA[i] + offB[i] - Z (double -> f32)
    const int rbase = cta * ROWS_PER_CTA;
    if (threadIdx.x < ROWS_PER_CTA) {
        int row = rbase + threadIdx.x;
        k_sm[threadIdx.x] = (float)(g_offA[row] + g_offB[row] - Zd);
    }
    __syncthreads();

    // ---- marginals: out = a_hat(out) + b_hat - scores + K[row]
    //      row-partitioned: this CTA streams rows [rbase, rbase+64)
    {
        const float4* b4 = (const float4*)g_beta;
        const float4* s4 = (const float4*)scores;
        float4* o4 = (float4*)out;
        const size_t base4 = (size_t)rbase * (C/4);
        const int    n4    = ROWS_PER_CTA * (C/4);        // 16384 float4
        for (int idx = threadIdx.x; idx < n4; idx += NTHREADS) {
            int   rl = idx >> 8;                          // local row (C/4 = 256)
            float K  = k_sm[rl];
            size_t i = base4 + idx;
            float4 av = __ldcg(&o4[i]);
            float4 b  = __ldcg(&b4[i]);
            float4 s  = __ldg(&s4[i]);
            float4 r;
            r.x = av.x + b.x - s.x + K;
            r.y = av.y + b.y - s.y + K;
            r.z = av.z + b.z - s.z + K;
            r.w = av.w + b.w - s.w + K;
            o4[i] = r;
        }
    }
}

extern "C" void kernel_launch(void* const* d_in, const int* in_sizes, int n_in,
                              void* d_out, int out_size) {
    const float* scores = (const float*)d_in[0];   // [8192*1024] f32
    const float* T      = (const float*)d_in[1];   // [1024*1024] f32
    float* out = (float*)d_out;                    // [8192*1024] f32

    crf_init<<<(C*C + 255) / 256, 256>>>(T);
    crf_main<<<NCTA_TOTAL, NTHREADS>>>(scores, out);
}

// round 8
// speedup vs baseline: 1.4963x; 1.4276x over previous
#include <cuda_runtime.h>
#include <math.h>

#define NSENT 8192
#define C     1024
#define NCTA  64                 // CTAs per direction
#define COLS  16                 // columns owned per CTA (one per warp)
#define NTHREADS 512             // 16 warps
#define NCTA_TOTAL (2*NCTA)
#define FSTRIDE 8
#define ROWS_PER_CTA (NSENT / NCTA_TOTAL)   // 64 rows per CTA in epilogue

typedef unsigned long long u64;

// -------- device scratch (no allocations allowed) --------
__device__ float    g_E [C*C];          // exp(T) row-major [k][j]   (beta)
__device__ float    g_ET[C*C];          // transpose [j][k]          (alpha)
__device__ float    g_beta[(size_t)NSENT*C];     // centered beta
// self-tagged q pairs, STRONG 8B each: low32 = value bits, high32 = tag
__device__ u64      g_pair[2][2][C];    // [dir][buf][class]
__device__ double   g_offA[NSENT];      // alpha row offsets (double)
__device__ double   g_offB[NSENT];      // beta row offsets
__device__ double   g_Zbase;            // C_{N-1} for alpha
__device__ unsigned g_jflags[NCTA_TOTAL*FSTRIDE];// join barrier flags

__device__ __forceinline__ unsigned ld_acq(const unsigned* p) {
    unsigned v;
    asm volatile("ld.acquire.gpu.global.u32 %0, [%1];" : "=r"(v) : "l"(p) : "memory");
    return v;
}
__device__ __forceinline__ void st_rel(unsigned* p, unsigned v) {
    asm volatile("st.release.gpu.global.u32 [%0], %1;" :: "l"(p), "r"(v) : "memory");
}
// MORALLY STRONG 8B tagged-pair ops: aligned <=64b strong => single-copy atomic
__device__ __forceinline__ void st_pair_rel(u64* p, float val, unsigned tag) {
    u64 u = ((u64)tag << 32) | (u64)__float_as_uint(val);
    asm volatile("st.release.gpu.global.b64 [%0], %1;" :: "l"(p), "l"(u) : "memory");
}
__device__ __forceinline__ u64 ld_pair_acq(const u64* p) {
    u64 u;
    asm volatile("ld.acquire.gpu.global.b64 %0, [%1];" : "=l"(u) : "l"(p) : "memory");
    return u;
}
__device__ __forceinline__ float frcp(float x) {
    float r;
    asm("rcp.approx.f32 %0, %1;" : "=f"(r) : "f"(x));
    return r;
}

// -------- init kernel: E = exp(T), E^T, reset pair tags / flags --------
__global__ void crf_init(const float* __restrict__ T) {
    int idx = blockIdx.x * blockDim.x + threadIdx.x;
    if (idx < C*C) {
        float e = expf(T[idx]);
        g_E[idx] = e;
        int k = idx / C, j = idx % C;
        g_ET[j*C + k] = e;
    }
    if (idx < 2*2*C) ((u64*)g_pair)[idx] = 0ull;
    if (idx < NCTA_TOTAL*FSTRIDE) g_jflags[idx] = 0u;
}

// -------- persistent forward+backward kernel --------
__global__ void __launch_bounds__(NTHREADS) crf_main(const float* __restrict__ scores,
                                                     float* __restrict__ out) {
    const int  cta    = blockIdx.x;
    const bool isBeta = (cta >= NCTA);
    const int  dir    = isBeta ? 1 : 0;
    const int  grp    = isBeta ? (cta - NCTA) : cta;
    const int  warp   = threadIdx.x >> 5;
    const int  lane   = threadIdx.x & 31;
    const int  j      = grp * COLS + warp;    // column (alpha) / row (beta) owned

    __shared__ float p_sm[2][C];              // double-buffered q vector
    __shared__ float redsum[COLS];
    __shared__ float k_sm[ROWS_PER_CTA];

    // E coefficients for this warp's column, 32 regs/thread, loaded once.
    float4 Ereg[8];
    {
        const float* Emat = isBeta ? g_E : g_ET;
        const float4* Erow = (const float4*)(Emat + (size_t)j * C);
        #pragma unroll
        for (int u = 0; u < 8; u++) Ereg[u] = Erow[u*32 + lane];
    }

    float*  rowsOut = isBeta ? g_beta : out;   // centered alpha -> d_out
    double* offArr  = isBeta ? g_offB : g_offA;

    double Cd = 0.0;
    const bool keeper = (grp == 0 && warp == 0);   // checked under lane==0

    // ---- step 0: publish q0 = exp(scores[row0]) with tag 1 into buffer 0
    float s_pref = 0.0f, es_pref = 0.0f;
    {
        const int row0 = isBeta ? (NSENT - 1) : 0;
        if (lane == 0) {
            float a0 = __ldg(&scores[(size_t)row0 * C + j]);
            rowsOut[(size_t)row0 * C + j] = a0;          // centered (offset 0)
            st_pair_rel(&g_pair[dir][0][j], expf(a0), 1u);
            const int row1 = isBeta ? (NSENT - 2) : 1;
            s_pref = __ldg(&scores[(size_t)row1 * C + j]);
            es_pref = expf(s_pref);
            if (keeper) offArr[row0] = 0.0;
        }
    }

    // ---- main recurrence: 8191 dependent rounds, strong tagged pairs
    for (int t = 1; t < NSENT; t++) {
        const int row = isBeta ? (NSENT - 1 - t) : t;
        const int buf = (t - 1) & 1;

        float s_val  = s_pref;     // score of row t (lane0 meaningful)
        float es_val = es_pref;    // exp(score) of row t (lane0 meaningful)
        if (lane == 0) {
            int tn = (t + 1 < NSENT) ? (t + 1) : t;
            int rown = isBeta ? (NSENT - 1 - tn) : tn;
            s_pref = __ldg(&scores[(size_t)rown * C + j]);
        }

        // poll + stage: all 512 threads, 2 adjacent slots each, acquire pairs
        {
            const u64* base = g_pair[dir][buf] + threadIdx.x * 2;
            const unsigned want = (unsigned)t;
            u64 a, b;
            do {
                a = ld_pair_acq(base + 0);
                b = ld_pair_acq(base + 1);
            } while (((unsigned)(a >> 32) != want) | ((unsigned)(b >> 32) != want));
            p_sm[buf][threadIdx.x*2 + 0] = __uint_as_float((unsigned)a);
            p_sm[buf][threadIdx.x*2 + 1] = __uint_as_float((unsigned)b);
        }
        __syncthreads();     // the ONLY per-step CTA barrier

        // matvec + running max of q (every warp scans the full vector)
        float ax = 0.f, ay = 0.f, az = 0.f, aw = 0.f;
        float mx = 0.f, my = 0.f, mz = 0.f, mw = 0.f;
        const float4* p4 = (const float4*)p_sm[buf];
        #pragma unroll
        for (int u = 0; u < 8; u++) {
            float4 p = p4[u*32 + lane];
            ax = fmaf(p.x, Ereg[u].x, ax);  mx = fmaxf(mx, p.x);
            ay = fmaf(p.y, Ereg[u].y, ay);  my = fmaxf(my, p.y);
            az = fmaf(p.z, Ereg[u].z, az);  mz = fmaxf(mz, p.z);
            aw = fmaf(p.w, Ereg[u].w, aw);  mw = fmaxf(mw, p.w);
        }
        float acc = (ax + ay) + (az + aw);
        float mxp = fmaxf(fmaxf(mx, my), fmaxf(mz, mw));
        #pragma unroll
        for (int s = 16; s > 0; s >>= 1) {
            acc += __shfl_xor_sync(0xFFFFFFFFu, acc, s);
            mxp  = fmaxf(mxp, __shfl_xor_sync(0xFFFFFFFFu, mxp, s));
        }

        if (lane == 0) {
            // ---- ON critical path: 1 rcp + 2 muls + release-publish
            float r = frcp(mxp);              // identical bitwise in every CTA
            float q = es_val * acc * r;       // q_t = e^s * acc / max(q_{t-1})
            st_pair_rel(&g_pair[dir][t & 1][j], q, (unsigned)(t + 1));
            // ---- OFF critical path
            rowsOut[(size_t)row * C + j] = s_val + logf(acc);  // ahat = s + la
            if (keeper) {
                offArr[row] = Cd;             // offset of row t is C_{t-1}
                Cd -= (double)logf(r);        // C_t = C_{t-1} - log r
            }
            es_pref = expf(s_pref);           // e^{score[row t+1]}
        }
    }

    // final rowsOut/offArr stores must happen-before the join release
    __syncthreads();
    if (keeper && threadIdx.x == 0 && !isBeta) g_Zbase = Cd;   // C_{N-1} alpha

    // ---- join both directions (release/acquire flag barrier)
    if (threadIdx.x == 0) st_rel(&g_jflags[cta*FSTRIDE], 1u);
    if (threadIdx.x < NCTA_TOTAL) {
        const unsigned* fp = &g_jflags[threadIdx.x * FSTRIDE];
        while (ld_acq(fp) < 1u) { }
    }
    __syncthreads();

    // ---- Z = Zbase + log(sum q_final), computed redundantly by every CTA
    double Zd;
    {
        // final alpha pairs live in buffer (NSENT-1)&1 = 1
        u64 v0 = __ldcg((const u64*)&g_pair[0][1][threadIdx.x * 2]);
        u64 v1 = __ldcg((const u64*)&g_pair[0][1][threadIdx.x * 2 + 1]);
        float zs = __uint_as_float((unsigned)v0) + __uint_as_float((unsigned)v1);
        #pragma unroll
        for (int s = 16; s > 0; s >>= 1)
            zs += __shfl_xor_sync(0xFFFFFFFFu, zs, s);
        if (lane == 0) redsum[warp] = zs;
        __syncthreads();
        if (warp == 0) {
            float s = (lane < COLS) ? redsum[lane] : 0.0f;
            #pragma unroll
            for (int sh = 8; sh > 0; sh >>= 1)
                s += __shfl_xor_sync(0xFFFFFFFFu, s, sh);
            if (lane == 0) redsum[0] = s;
        }
        __syncthreads();
        Zd = g_Zbase + (double)logf(redsum[0]);
    }

    // ---- per-row combine constants K[i] = offA[i] + offB[i] - Z
    const int rbase = cta * ROWS_PER_CTA;
    if (threadIdx.x < ROWS_PER_CTA) {
        int row = rbase + threadIdx.x;
        k_sm[threadIdx.x] = (float)(g_offA[row] + g_offB[row] - Zd);
    }
    __syncthreads();

    // ---- marginals: out = a_hat(out) + b_hat - scores + K[row]
    {
        const float4* b4 = (const float4*)g_beta;
        const float4* s4 = (const float4*)scores;
        float4* o4 = (float4*)out;
        const size_t base4 = (size_t)rbase * (C/4);
        const int    n4    = ROWS_PER_CTA * (C/4);
        for (int idx = threadIdx.x; idx < n4; idx += NTHREADS) {
            int   rl = idx >> 8;
            float K  = k_sm[rl];
            size_t i = base4 + idx;
            float4 av = __ldcg(&o4[i]);
            float4 b  = __ldcg(&b4[i]);
            float4 s  = __ldg(&s4[i]);
            float4 r;
            r.x = av.x + b.x - s.x + K;
            r.y = av.y + b.y - s.y + K;
            r.z = av.z + b.z - s.z + K;
            r.w = av.w + b.w - s.w + K;
            o4[i] = r;
        }
    }
}

extern "C" void kernel_launch(void* const* d_in, const int* in_sizes, int n_in,
                              void* d_out, int out_size) {
    const float* scores = (const float*)d_in[0];   // [8192*1024] f32
    const float* T      = (const float*)d_in[1];   // [1024*1024] f32
    float* out = (float*)d_out;                    // [8192*1024] f32

    crf_init<<<(C*C + 255) / 256, 256>>>(T);
    crf_main<<<NCTA_TOTAL, NTHREADS>>>(scores, out);
}

// round 9
// speedup vs baseline: 1.5017x; 1.0037x over previous
#include <cuda_runtime.h>
#include <math.h>

#define NSENT 8192
#define C     1024
#define NCTA  64                 // CTAs per direction
#define COLS  16                 // columns owned per CTA (one per warp)
#define NTHREADS 512             // 16 warps
#define NCTA_TOTAL (2*NCTA)
#define FSTRIDE 8
#define ROWS_PER_CTA (NSENT / NCTA_TOTAL)   // 64 rows per CTA in epilogue

typedef unsigned long long u64;

// -------- device scratch (no allocations allowed) --------
__device__ float    g_E [C*C];          // exp(T) row-major [k][j]   (beta)
__device__ float    g_ET[C*C];          // transpose [j][k]          (alpha)
__device__ float    g_beta[(size_t)NSENT*C];     // centered beta
__device__ float    g_q[2][2][C];       // [dir][buf][class] scaled probs (plain f32)
__device__ unsigned g_cnt[2][NCTA*FSTRIDE];      // cumulative publish counters
__device__ double   g_offA[NSENT];      // alpha row offsets (double)
__device__ double   g_offB[NSENT];      // beta row offsets
__device__ double   g_Zbase;            // C_{N-1} for alpha
__device__ unsigned g_jflags[NCTA_TOTAL*FSTRIDE];// join barrier flags

__device__ __forceinline__ unsigned ld_acq(const unsigned* p) {
    unsigned v;
    asm volatile("ld.acquire.gpu.global.u32 %0, [%1];" : "=r"(v) : "l"(p) : "memory");
    return v;
}
__device__ __forceinline__ void st_rel(unsigned* p, unsigned v) {
    asm volatile("st.release.gpu.global.u32 [%0], %1;" :: "l"(p), "r"(v) : "memory");
}
__device__ __forceinline__ void st_f32_cg(float* p, float v) {
    asm volatile("st.global.cg.f32 [%0], %1;" :: "l"(p), "f"(v) : "memory");
}
// release-RMW: orders this thread's prior stores; forms release sequence
__device__ __forceinline__ void red_rel_add(unsigned* p, unsigned v) {
    asm volatile("red.release.gpu.global.add.u32 [%0], %1;" :: "l"(p), "r"(v) : "memory");
}
__device__ __forceinline__ float frcp(float x) {
    float r;
    asm("rcp.approx.f32 %0, %1;" : "=f"(r) : "f"(x));
    return r;
}

// -------- init kernel --------
__global__ void crf_init(const float* __restrict__ T) {
    int idx = blockIdx.x * blockDim.x + threadIdx.x;
    if (idx < C*C) {
        float e = expf(T[idx]);
        g_E[idx] = e;
        int k = idx / C, j = idx % C;
        g_ET[j*C + k] = e;
    }
    if (idx < 2*NCTA*FSTRIDE) { g_cnt[0][idx % (NCTA*FSTRIDE)] = 0u; }
    if (idx < NCTA*FSTRIDE)   { g_cnt[1][idx] = 0u; }
    if (idx < NCTA_TOTAL*FSTRIDE) g_jflags[idx] = 0u;
}

// -------- persistent forward+backward kernel --------
__global__ void __launch_bounds__(NTHREADS) crf_main(const float* __restrict__ scores,
                                                     float* __restrict__ out) {
    const int  cta    = blockIdx.x;
    const bool isBeta = (cta >= NCTA);
    const int  dir    = isBeta ? 1 : 0;
    const int  grp    = isBeta ? (cta - NCTA) : cta;
    const int  warp   = threadIdx.x >> 5;
    const int  lane   = threadIdx.x & 31;
    const int  j      = grp * COLS + warp;    // column (alpha) / row (beta) owned

    __shared__ float p_sm[2][C];              // double-buffered q vector
    __shared__ float redsum[COLS];
    __shared__ float k_sm[ROWS_PER_CTA];

    // E coefficients for this warp's column, 32 regs/thread, loaded once.
    float4 Ereg[8];
    {
        const float* Emat = isBeta ? g_E : g_ET;
        const float4* Erow = (const float4*)(Emat + (size_t)j * C);
        #pragma unroll
        for (int u = 0; u < 8; u++) Ereg[u] = Erow[u*32 + lane];
    }

    float*    rowsOut = isBeta ? g_beta : out;   // centered alpha -> d_out
    double*   offArr  = isBeta ? g_offB : g_offA;
    unsigned* cntArr  = g_cnt[dir];

    double Cd = 0.0;
    const bool keeper = (grp == 0 && warp == 0);   // checked under lane==0

    // ---- step 0: publish q0 = exp(scores[row0]) into buffer 0, announce
    float s_pref = 0.0f, es_pref = 0.0f;
    {
        const int row0 = isBeta ? (NSENT - 1) : 0;
        if (lane == 0) {
            float a0 = __ldg(&scores[(size_t)row0 * C + j]);
            rowsOut[(size_t)row0 * C + j] = a0;          // centered (offset 0)
            st_f32_cg(&g_q[dir][0][j], expf(a0));
            red_rel_add(&cntArr[grp*FSTRIDE], 1u);       // announce
            const int row1 = isBeta ? (NSENT - 2) : 1;
            s_pref = __ldg(&scores[(size_t)row1 * C + j]);
            es_pref = expf(s_pref);
            if (keeper) offArr[row0] = 0.0;
        }
    }

    // ---- main recurrence: 8191 dependent rounds
    for (int t = 1; t < NSENT; t++) {
        const int row = isBeta ? (NSENT - 1 - t) : t;
        const int buf = (t - 1) & 1;

        float s_val  = s_pref;     // score of row t (lane0 meaningful)
        float es_val = es_pref;    // exp(score) of row t (lane0 meaningful)
        if (lane == 0) {
            int tn = (t + 1 < NSENT) ? (t + 1) : t;
            int rown = isBeta ? (NSENT - 1 - tn) : tn;
            s_pref = __ldg(&scores[(size_t)rown * C + j]);
        }

        // detect + fetch: threads 0..63 poll one counter each, then fetch
        // that producer's 64B (16 floats) coalesced.
        if (threadIdx.x < NCTA) {
            const int g = threadIdx.x;
            const unsigned want = (unsigned)(16 * t);    // 16 increments/step
            while (ld_acq(&cntArr[g*FSTRIDE]) < want) { }
            const float4* src = (const float4*)(g_q[dir][buf] + g*16);
            float4 v0 = __ldcg(&src[0]);
            float4 v1 = __ldcg(&src[1]);
            float4 v2 = __ldcg(&src[2]);
            float4 v3 = __ldcg(&src[3]);
            float4* dst = (float4*)&p_sm[buf][g*16];
            dst[0] = v0; dst[1] = v1; dst[2] = v2; dst[3] = v3;
        }
        __syncthreads();     // the ONLY per-step CTA barrier

        // matvec + running max of q (every warp scans the full vector)
        float ax = 0.f, ay = 0.f, az = 0.f, aw = 0.f;
        float mx = 0.f, my = 0.f, mz = 0.f, mw = 0.f;
        const float4* p4 = (const float4*)p_sm[buf];
        #pragma unroll
        for (int u = 0; u < 8; u++) {
            float4 p = p4[u*32 + lane];
            ax = fmaf(p.x, Ereg[u].x, ax);  mx = fmaxf(mx, p.x);
            ay = fmaf(p.y, Ereg[u].y, ay);  my = fmaxf(my, p.y);
            az = fmaf(p.z, Ereg[u].z, az);  mz = fmaxf(mz, p.z);
            aw = fmaf(p.w, Ereg[u].w, aw);  mw = fmaxf(mw, p.w);
        }
        float acc = (ax + ay) + (az + aw);
        float mxp = fmaxf(fmaxf(mx, my), fmaxf(mz, mw));
        #pragma unroll
        for (int s = 16; s > 0; s >>= 1) {
            acc += __shfl_xor_sync(0xFFFFFFFFu, acc, s);
            mxp  = fmaxf(mxp, __shfl_xor_sync(0xFFFFFFFFu, mxp, s));
        }

        if (lane == 0) {
            // ---- ON critical path: rcp + 2 muls + store + release-red
            float r = frcp(mxp);              // bitwise identical in every CTA
            float q = es_val * acc * r;       // q_t = e^s * acc / max(q_{t-1})
            st_f32_cg(&g_q[dir][t & 1][j], q);
            red_rel_add(&cntArr[grp*FSTRIDE], 1u);
            // ---- OFF critical path
            rowsOut[(size_t)row * C + j] = s_val + logf(acc);  // ahat = s + la
            if (keeper) {
                offArr[row] = Cd;             // offset of row t is C_{t-1}
                Cd -= (double)logf(r);        // C_t = C_{t-1} - log r
            }
            es_pref = expf(s_pref);           // e^{score[row t+1]}
        }
    }

    // final rowsOut/offArr stores must happen-before the join release
    __syncthreads();
    if (keeper && threadIdx.x == 0 && !isBeta) g_Zbase = Cd;   // C_{N-1} alpha

    // ---- join both directions (release/acquire flag barrier)
    if (threadIdx.x == 0) st_rel(&g_jflags[cta*FSTRIDE], 1u);
    if (threadIdx.x < NCTA_TOTAL) {
        const unsigned* fp = &g_jflags[threadIdx.x * FSTRIDE];
        while (ld_acq(fp) < 1u) { }
    }
    __syncthreads();

    // ---- Z = Zbase + log(sum q_final), computed redundantly by every CTA
    double Zd;
    {
        // final alpha q lives in buffer (NSENT-1)&1 = 1
        const float2* qz = (const float2*)g_q[0][1];
        float2 v = __ldcg(&qz[threadIdx.x]);
        float zs = v.x + v.y;
        #pragma unroll
        for (int s = 16; s > 0; s >>= 1)
            zs += __shfl_xor_sync(0xFFFFFFFFu, zs, s);
        if (lane == 0) redsum[warp] = zs;
        __syncthreads();
        if (warp == 0) {
            float s = (lane < COLS) ? redsum[lane] : 0.0f;
            #pragma unroll
            for (int sh = 8; sh > 0; sh >>= 1)
                s += __shfl_xor_sync(0xFFFFFFFFu, s, sh);
            if (lane == 0) redsum[0] = s;
        }
        __syncthreads();
        Zd = g_Zbase + (double)logf(redsum[0]);
    }

    // ---- per-row combine constants K[i] = offA[i] + offB[i] - Z
    const int rbase = cta * ROWS_PER_CTA;
    if (threadIdx.x < ROWS_PER_CTA) {
        int row = rbase + threadIdx.x;
        k_sm[threadIdx.x] = (float)(g_offA[row] + g_offB[row] - Zd);
    }
    __syncthreads();

    // ---- marginals: out = a_hat(out) + b_hat - scores + K[row]
    {
        const float4* b4 = (const float4*)g_beta;
        const float4* s4 = (const float4*)scores;
        float4* o4 = (float4*)out;
        const size_t base4 = (size_t)rbase * (C/4);
        const int    n4    = ROWS_PER_CTA * (C/4);
        for (int idx = threadIdx.x; idx < n4; idx += NTHREADS) {
            int   rl = idx >> 8;
            float K  = k_sm[rl];
            size_t i = base4 + idx;
            float4 av = __ldcg(&o4[i]);
            float4 b  = __ldcg(&b4[i]);
            float4 s  = __ldg(&s4[i]);
            float4 r;
            r.x = av.x + b.x - s.x + K;
            r.y = av.y + b.y - s.y + K;
            r.z = av.z + b.z - s.z + K;
            r.w = av.w + b.w - s.w + K;
            o4[i] = r;
        }
    }
}

extern "C" void kernel_launch(void* const* d_in, const int* in_sizes, int n_in,
                              void* d_out, int out_size) {
    const float* scores = (const float*)d_in[0];   // [8192*1024] f32
    const float* T      = (const float*)d_in[1];   // [1024*1024] f32
    float* out = (float*)d_out;                    // [8192*1024] f32

    crf_init<<<(C*C + 255) / 256, 256>>>(T);
    crf_main<<<NCTA_TOTAL, NTHREADS>>>(scores, out);
}